// round 3
// baseline (speedup 1.0000x reference)
#include <cuda_runtime.h>
#include <math.h>
#include <stdint.h>

#define SEQ    4096
#define DMODEL 1024
#define NH     16
#define HS     64

// Scratch (no cudaMalloc allowed). Q/K/V hold tf32-rounded values (bit pattern
// in fp32) — written by gemm epilogue so attention loads need no cvt.
__device__ float g_Q[NH * SEQ * HS];
__device__ float g_K[NH * SEQ * HS];
__device__ float g_V[NH * SEQ * HS];
__device__ float g_attn[SEQ * DMODEL];

__device__ __forceinline__ uint32_t f2tf32(float x) {
    uint32_t r;
    asm("cvt.rna.tf32.f32 %0, %1;" : "=r"(r) : "f"(x));
    return r;
}
__device__ __forceinline__ float tf32f(float x) {
    return __uint_as_float(f2tf32(x));
}
__device__ __forceinline__ uint32_t fu(float x) { return __float_as_uint(x); }

__device__ __forceinline__ void mma8(float* c,
    uint32_t a0, uint32_t a1, uint32_t a2, uint32_t a3,
    uint32_t b0, uint32_t b1)
{
    asm volatile(
        "mma.sync.aligned.m16n8k8.row.col.f32.tf32.tf32.f32 "
        "{%0,%1,%2,%3},{%4,%5,%6,%7},{%8,%9},{%0,%1,%2,%3};"
        : "+f"(c[0]), "+f"(c[1]), "+f"(c[2]), "+f"(c[3])
        : "r"(a0), "r"(a1), "r"(a2), "r"(a3), "r"(b0), "r"(b1));
}

// ---------------------------------------------------------------------------
// tf32 tensor-core GEMM: C[M,N] = A[M,1024] * B[N,1024]^T + bias[N]
// MODE 0: A = x, scatter tf32-rounded into g_Q/g_K/g_V (N = 3072)
// MODE 1: A = g_attn, write fp32 C = d_out (N = 1024)
// 128x128 block, BK=32, 256 threads (8 warps), warp tile 64x32.
// Register double-buffer: next K-tile global loads overlap current compute.
// ---------------------------------------------------------------------------
template <int MODE>
__global__ __launch_bounds__(256) void gemm_tc(
    const float* __restrict__ A, const float* __restrict__ B,
    const float* __restrict__ bias, float* __restrict__ C)
{
    __shared__ float As[128 * 36];
    __shared__ float Bs[128 * 36];

    const float* __restrict__ Ap = (MODE == 0) ? A : g_attn;
    const int bm = blockIdx.y * 128;
    const int bn = blockIdx.x * 128;
    const int t    = threadIdx.x;
    const int warp = t >> 5;
    const int lane = t & 31;
    const int wm = (warp >> 2) * 64;
    const int wn = (warp & 3) * 32;
    const int lr = lane >> 2;
    const int lc = lane & 3;

    float c[4][4][4];
#pragma unroll
    for (int mf = 0; mf < 4; mf++)
#pragma unroll
        for (int nf = 0; nf < 4; nf++)
#pragma unroll
            for (int r = 0; r < 4; r++) c[mf][nf][r] = 0.f;

    float4 stA[4], stB[4];
#pragma unroll
    for (int j = 0; j < 4; j++) {          // prefetch k0 = 0
        int idx = t + j * 256;
        int row = idx >> 3;
        int col = (idx & 7) * 4;
        stA[j] = *(const float4*)(Ap + (size_t)(bm + row) * DMODEL + col);
        stB[j] = *(const float4*)(B  + (size_t)(bn + row) * DMODEL + col);
    }

    for (int k0 = 0; k0 < DMODEL; k0 += 32) {
        __syncthreads();
#pragma unroll
        for (int j = 0; j < 4; j++) {
            int idx = t + j * 256;
            int row = idx >> 3;
            int col = (idx & 7) * 4;
            float4 wa, wb;
            wa.x = tf32f(stA[j].x); wa.y = tf32f(stA[j].y);
            wa.z = tf32f(stA[j].z); wa.w = tf32f(stA[j].w);
            wb.x = tf32f(stB[j].x); wb.y = tf32f(stB[j].y);
            wb.z = tf32f(stB[j].z); wb.w = tf32f(stB[j].w);
            *(float4*)(As + row * 36 + col) = wa;
            *(float4*)(Bs + row * 36 + col) = wb;
        }
        __syncthreads();

        if (k0 + 32 < DMODEL) {            // prefetch next K-tile (overlaps mma)
#pragma unroll
            for (int j = 0; j < 4; j++) {
                int idx = t + j * 256;
                int row = idx >> 3;
                int col = (idx & 7) * 4;
                stA[j] = *(const float4*)(Ap + (size_t)(bm + row) * DMODEL + k0 + 32 + col);
                stB[j] = *(const float4*)(B  + (size_t)(bn + row) * DMODEL + k0 + 32 + col);
            }
        }

#pragma unroll
        for (int kk = 0; kk < 32; kk += 8) {
            uint32_t a[4][4], b[4][2];
#pragma unroll
            for (int mf = 0; mf < 4; mf++) {
                int m0 = wm + mf * 16 + lr;
                a[mf][0] = fu(As[(m0    ) * 36 + kk + lc    ]);
                a[mf][1] = fu(As[(m0 + 8) * 36 + kk + lc    ]);
                a[mf][2] = fu(As[(m0    ) * 36 + kk + lc + 4]);
                a[mf][3] = fu(As[(m0 + 8) * 36 + kk + lc + 4]);
            }
#pragma unroll
            for (int nf = 0; nf < 4; nf++) {
                int n0 = wn + nf * 8 + lr;
                b[nf][0] = fu(Bs[n0 * 36 + kk + lc    ]);
                b[nf][1] = fu(Bs[n0 * 36 + kk + lc + 4]);
            }
#pragma unroll
            for (int mf = 0; mf < 4; mf++)
#pragma unroll
                for (int nf = 0; nf < 4; nf++)
                    mma8(c[mf][nf], a[mf][0], a[mf][1], a[mf][2], a[mf][3],
                         b[nf][0], b[nf][1]);
        }
    }

#pragma unroll
    for (int mf = 0; mf < 4; mf++) {
#pragma unroll
        for (int nf = 0; nf < 4; nf++) {
            int n = bn + wn + nf * 8 + 2 * lc;
            float b0 = bias[n], b1 = bias[n + 1];
#pragma unroll
            for (int rh = 0; rh < 2; rh++) {
                int m = bm + wm + mf * 16 + lr + rh * 8;
                float2 v;
                v.x = c[mf][nf][rh * 2 + 0] + b0;
                v.y = c[mf][nf][rh * 2 + 1] + b1;
                if (MODE == 0) {
                    v.x = tf32f(v.x);      // pre-round for attention mma inputs
                    v.y = tf32f(v.y);
                    int sel = n >> 10;
                    int nn  = n & 1023;
                    float* dst = (sel == 0) ? g_Q : (sel == 1) ? g_K : g_V;
                    *(float2*)&dst[((size_t)(nn >> 6) * SEQ + m) * HS + (nn & 63)] = v;
                } else {
                    *(float2*)&C[(size_t)m * DMODEL + n] = v;
                }
            }
        }
    }
}

// ---------------------------------------------------------------------------
// tf32 flash attention. Grid (S/128, NH), 256 threads (8 warps).
// 128-row Q tile, 64x64 KV tiles, register-double-buffered KV prefetch.
// Warp w owns q-rows [w*16, w*16+16). Per-warp causal loop bound avoids
// fully-masked warps (NaN-safe). Q/K/V are pre-rounded tf32 -> raw copies.
// ---------------------------------------------------------------------------
#define BQ   128
#define QSTR 68   // == 4 mod 32: conflict-free for A/B frag pattern
#define VSTR 72   // == 8 mod 32: conflict-free for V B-frag pattern
#define ATTN_SMEM ((BQ * QSTR + 64 * QSTR + 64 * VSTR + BQ * QSTR) * 4)

__global__ __launch_bounds__(256) void attn_tc(const int* __restrict__ cmask)
{
    extern __shared__ float sm[];
    float* Qs = sm;                       // [128][QSTR]
    float* Ks = Qs + BQ * QSTR;           // [64][QSTR]
    float* Vs = Ks + 64 * QSTR;           // [64][VSTR]
    float* Ps = Vs + 64 * VSTR;           // [128][QSTR]

    const int h   = blockIdx.y;
    const int it  = gridDim.x - 1 - blockIdx.x;   // big tiles first
    const int qi0 = it * BQ;
    const int t    = threadIdx.x;
    const int warp = t >> 5;
    const int lane = t & 31;
    const int lr = lane >> 2;
    const int lc = lane & 3;
    const int w16 = warp * 16;
    const int causal = cmask ? cmask[0] : 1;

    // Q tile: 128x64 = 2048 float4, raw copy (already tf32)
    {
        const float* src = g_Q + ((size_t)h * SEQ + qi0) * HS;
#pragma unroll
        for (int j = 0; j < 8; j++) {
            int idx = t + j * 256;
            int row = idx >> 4;
            int col = (idx & 15) * 4;
            *(float4*)(Qs + row * QSTR + col) = ((const float4*)src)[idx];
        }
    }

    float mrow0 = -INFINITY, mrow1 = -INFINITY, l0 = 0.f, l1 = 0.f;
    float O[8][4];
#pragma unroll
    for (int nf = 0; nf < 8; nf++)
#pragma unroll
        for (int r = 0; r < 4; r++) O[nf][r] = 0.f;

    const int jt_end_blk = causal ? 2 * it + 1 : (SEQ / 64 - 1);
    const int jt_end_w   = causal ? 2 * it + (warp >> 2) : (SEQ / 64 - 1);

    const float* kbase = g_K + (size_t)h * SEQ * HS;
    const float* vbase = g_V + (size_t)h * SEQ * HS;

    float4 stK[4], stV[4];
#pragma unroll
    for (int j = 0; j < 4; j++) {          // prefetch tile 0
        int idx = t + j * 256;
        stK[j] = ((const float4*)kbase)[idx];
        stV[j] = ((const float4*)vbase)[idx];
    }

    for (int jt = 0; jt <= jt_end_blk; jt++) {
        __syncthreads();                   // prev iter done with Ks/Vs
#pragma unroll
        for (int j = 0; j < 4; j++) {
            int idx = t + j * 256;
            int row = idx >> 4;
            int col = (idx & 15) * 4;
            *(float4*)(Ks + row * QSTR + col) = stK[j];
            *(float4*)(Vs + row * VSTR + col) = stV[j];
        }
        __syncthreads();

        if (jt < jt_end_blk) {             // prefetch next KV (overlaps compute)
            const float* kn = kbase + (size_t)(jt + 1) * 64 * HS;
            const float* vn = vbase + (size_t)(jt + 1) * 64 * HS;
#pragma unroll
            for (int j = 0; j < 4; j++) {
                int idx = t + j * 256;
                stK[j] = ((const float4*)kn)[idx];
                stV[j] = ((const float4*)vn)[idx];
            }
        }

        if (jt <= jt_end_w) {
            // ---- S = Q K^T (16x64 per warp) ----
            float c[8][4];
#pragma unroll
            for (int nf = 0; nf < 8; nf++)
#pragma unroll
                for (int r = 0; r < 4; r++) c[nf][r] = 0.f;

#pragma unroll
            for (int kk = 0; kk < HS; kk += 8) {
                uint32_t a0 = fu(Qs[(w16 + lr    ) * QSTR + kk + lc    ]);
                uint32_t a1 = fu(Qs[(w16 + lr + 8) * QSTR + kk + lc    ]);
                uint32_t a2 = fu(Qs[(w16 + lr    ) * QSTR + kk + lc + 4]);
                uint32_t a3 = fu(Qs[(w16 + lr + 8) * QSTR + kk + lc + 4]);
#pragma unroll
                for (int nf = 0; nf < 8; nf++) {
                    uint32_t b0 = fu(Ks[(nf * 8 + lr) * QSTR + kk + lc    ]);
                    uint32_t b1 = fu(Ks[(nf * 8 + lr) * QSTR + kk + lc + 4]);
                    mma8(c[nf], a0, a1, a2, a3, b0, b1);
                }
            }

            // ---- mask + scale ----
            const int row0 = qi0 + w16 + lr;
            const int row1 = row0 + 8;
            const bool diag = causal && (jt * 64 + 63 > qi0 + w16);
#pragma unroll
            for (int nf = 0; nf < 8; nf++) {
                int col = jt * 64 + nf * 8 + 2 * lc;
                c[nf][0] *= 0.125f; c[nf][1] *= 0.125f;
                c[nf][2] *= 0.125f; c[nf][3] *= 0.125f;
                if (diag) {
                    if (col     > row0) c[nf][0] = -INFINITY;
                    if (col + 1 > row0) c[nf][1] = -INFINITY;
                    if (col     > row1) c[nf][2] = -INFINITY;
                    if (col + 1 > row1) c[nf][3] = -INFINITY;
                }
            }

            // ---- online softmax (rows live in lane quads) ----
            float mx0 = -INFINITY, mx1 = -INFINITY;
#pragma unroll
            for (int nf = 0; nf < 8; nf++) {
                mx0 = fmaxf(mx0, fmaxf(c[nf][0], c[nf][1]));
                mx1 = fmaxf(mx1, fmaxf(c[nf][2], c[nf][3]));
            }
            mx0 = fmaxf(mx0, __shfl_xor_sync(0xffffffffu, mx0, 1));
            mx0 = fmaxf(mx0, __shfl_xor_sync(0xffffffffu, mx0, 2));
            mx1 = fmaxf(mx1, __shfl_xor_sync(0xffffffffu, mx1, 1));
            mx1 = fmaxf(mx1, __shfl_xor_sync(0xffffffffu, mx1, 2));

            const float mn0 = fmaxf(mrow0, mx0);
            const float mn1 = fmaxf(mrow1, mx1);
            const float al0 = __expf(mrow0 - mn0);
            const float al1 = __expf(mrow1 - mn1);
            float s0 = 0.f, s1 = 0.f;
#pragma unroll
            for (int nf = 0; nf < 8; nf++) {
                c[nf][0] = __expf(c[nf][0] - mn0); s0 += c[nf][0];
                c[nf][1] = __expf(c[nf][1] - mn0); s0 += c[nf][1];
                c[nf][2] = __expf(c[nf][2] - mn1); s1 += c[nf][2];
                c[nf][3] = __expf(c[nf][3] - mn1); s1 += c[nf][3];
            }
            s0 += __shfl_xor_sync(0xffffffffu, s0, 1);
            s0 += __shfl_xor_sync(0xffffffffu, s0, 2);
            s1 += __shfl_xor_sync(0xffffffffu, s1, 1);
            s1 += __shfl_xor_sync(0xffffffffu, s1, 2);
            l0 = l0 * al0 + s0;  l1 = l1 * al1 + s1;
            mrow0 = mn0;         mrow1 = mn1;
#pragma unroll
            for (int nf = 0; nf < 8; nf++) {
                O[nf][0] *= al0; O[nf][1] *= al0;
                O[nf][2] *= al1; O[nf][3] *= al1;
            }

            // ---- P -> smem (tf32), warp-private region ----
#pragma unroll
            for (int nf = 0; nf < 8; nf++) {
                float2 p0, p1;
                p0.x = tf32f(c[nf][0]); p0.y = tf32f(c[nf][1]);
                p1.x = tf32f(c[nf][2]); p1.y = tf32f(c[nf][3]);
                *(float2*)&Ps[(w16 + lr    ) * QSTR + nf * 8 + 2 * lc] = p0;
                *(float2*)&Ps[(w16 + lr + 8) * QSTR + nf * 8 + 2 * lc] = p1;
            }
            __syncwarp();

            // ---- O += P V ----
#pragma unroll
            for (int kk = 0; kk < 64; kk += 8) {
                uint32_t a0 = fu(Ps[(w16 + lr    ) * QSTR + kk + lc    ]);
                uint32_t a1 = fu(Ps[(w16 + lr + 8) * QSTR + kk + lc    ]);
                uint32_t a2 = fu(Ps[(w16 + lr    ) * QSTR + kk + lc + 4]);
                uint32_t a3 = fu(Ps[(w16 + lr + 8) * QSTR + kk + lc + 4]);
#pragma unroll
                for (int nf = 0; nf < 8; nf++) {
                    uint32_t b0 = fu(Vs[(kk + lc    ) * VSTR + nf * 8 + lr]);
                    uint32_t b1 = fu(Vs[(kk + lc + 4) * VSTR + nf * 8 + lr]);
                    mma8(O[nf], a0, a1, a2, a3, b0, b1);
                }
            }
        }
    }

    // ---- epilogue ----
    const float inv0 = 1.f / l0;
    const float inv1 = 1.f / l1;
#pragma unroll
    for (int nf = 0; nf < 8; nf++) {
        int col = h * HS + nf * 8 + 2 * lc;
        float2 v0, v1;
        v0.x = O[nf][0] * inv0; v0.y = O[nf][1] * inv0;
        v1.x = O[nf][2] * inv1; v1.y = O[nf][3] * inv1;
        *(float2*)&g_attn[(size_t)(qi0 + w16 + lr    ) * DMODEL + col] = v0;
        *(float2*)&g_attn[(size_t)(qi0 + w16 + lr + 8) * DMODEL + col] = v1;
    }
}

// ---------------------------------------------------------------------------
extern "C" void kernel_launch(void* const* d_in, const int* in_sizes, int n_in,
                              void* d_out, int out_size)
{
    const float* x     = (const float*)d_in[0];
    const float* w_qkv = (const float*)d_in[1];
    const float* b_qkv = (const float*)d_in[2];
    const float* w_o   = (const float*)d_in[3];
    const float* b_o   = (const float*)d_in[4];
    const int*   cmask = (n_in > 5) ? (const int*)d_in[5] : nullptr;

    cudaFuncSetAttribute(attn_tc,
                         cudaFuncAttributeMaxDynamicSharedMemorySize, ATTN_SMEM);

    gemm_tc<0><<<dim3(3072 / 128, SEQ / 128), 256>>>(x, w_qkv, b_qkv, nullptr);
    attn_tc<<<dim3(SEQ / BQ, NH), 256, ATTN_SMEM>>>(cmask);
    gemm_tc<1><<<dim3(DMODEL / 128, SEQ / 128), 256>>>(nullptr, w_o, b_o,
                                                       (float*)d_out);
}